// round 8
// baseline (speedup 1.0000x reference)
#include <cuda_runtime.h>
#include <cstdint>
#include <math.h>

#define WTOT 4096
#define CHUNK 64
#define HDIM 128
#define BATCH 64
#define NCHUNK (WTOT / CHUNK)
#define NPRE 512

__device__ __align__(16) float g_pvec[BATCH * NCHUNK * HDIM];
__device__ __align__(16) float g_psum[BATCH * NCHUNK];
__device__ __align__(16) float g_pre0[BATCH * 512];
__device__ __align__(16) float g_pre1[BATCH * 512];

__device__ __forceinline__ float warp_sum(float p) {
    #pragma unroll
    for (int o = 16; o > 0; o >>= 1) p += __shfl_down_sync(0xffffffffu, p, o);
    return p;
}

__device__ __forceinline__ float sigmoidf_(float x) {
    return 1.0f / (1.0f + expf(-x));
}

__device__ __forceinline__ float dot4(float4 a, float4 b) {
    return a.x * b.x + a.y * b.y + a.z * b.z + a.w * b.w;
}

// ---------------------------------------------------------------------------
// Kernel 1: blocks [0,NPRE) precompute hh gate halves; rest = register-
// resident attention pass (identical to R6 attention, which was sound).
// ---------------------------------------------------------------------------
__global__ void __launch_bounds__(256) attn_pre_kernel(
    const float* __restrict__ enc,
    const float* __restrict__ h0,
    const float* __restrict__ c0,
    const float* __restrict__ attW,
    const float* __restrict__ attb,
    const float* __restrict__ W_hh0,
    const float* __restrict__ b_ih0, const float* __restrict__ b_hh0,
    const float* __restrict__ W_hh1,
    const float* __restrict__ b_ih1, const float* __restrict__ b_hh1)
{
    const int tid  = threadIdx.x;
    const int lane = tid & 31;
    const int wrp  = tid >> 5;

    if (blockIdx.x < NPRE) {
        const int b  = blockIdx.x >> 3;
        const int k0 = (blockIdx.x & 7) * 64;
        const float4 hv0 = ((const float4*)(h0 + b * HDIM))[lane];
        const float4 hv1 = ((const float4*)(h0 + BATCH * HDIM + b * HDIM))[lane];
        #pragma unroll 4
        for (int t = 0; t < 8; t++) {
            const int k = k0 + wrp * 8 + t;
            float p0 = dot4(((const float4*)(W_hh0 + k * HDIM))[lane], hv0);
            p0 = warp_sum(p0);
            if (lane == 0) g_pre0[b * 512 + k] = p0 + b_ih0[k] + b_hh0[k];
        }
        #pragma unroll 4
        for (int t = 0; t < 8; t++) {
            const int k = k0 + wrp * 8 + t;
            float p1 = dot4(((const float4*)(W_hh1 + k * HDIM))[lane], hv1);
            p1 = warp_sum(p1);
            if (lane == 0) g_pre1[b * 512 + k] = p1 + b_ih1[k] + b_hh1[k];
        }
        return;
    }

    __shared__ float s_sh[CHUNK];
    __shared__ float e_sh[CHUNK];
    __shared__ float red[4];
    __shared__ float bias_sh;
    __shared__ float sprev_sh;
    __shared__ __align__(16) float partial[8][136];

    const int cid   = blockIdx.x - NPRE;
    const int chunk = cid & (NCHUNK - 1);
    const int b     = cid >> 6;
    const int start = chunk * CHUNK;

    const float4* src = (const float4*)(enc + ((size_t)b * WTOT + start) * HDIM);
    float4 v[8];
    #pragma unroll
    for (int i = 0; i < 8; i++) v[i] = src[tid + 256 * i];
    float4 vprev = make_float4(0.f, 0.f, 0.f, 0.f);
    if (wrp == 0 && start > 0)
        vprev = ((const float4*)(enc + ((size_t)b * WTOT + start - 1) * HDIM))[lane];

    const float4 wv = ((const float4*)attW)[lane];

    if (tid < HDIM) {
        float p = h0[BATCH * HDIM + b * HDIM + tid]
                * c0[BATCH * HDIM + b * HDIM + tid]
                * attW[HDIM + tid];
        p = warp_sum(p);
        if (lane == 0) red[wrp] = p;
    }
    __syncthreads();
    if (tid == 0) bias_sh = red[0] + red[1] + red[2] + red[3] + attb[0];

    float pr[8];
    #pragma unroll
    for (int i = 0; i < 8; i++) pr[i] = dot4(v[i], wv);
    float pprev = dot4(vprev, wv);
    __syncthreads();
    const float bias = bias_sh;
    #pragma unroll
    for (int i = 0; i < 8; i++) {
        float s = warp_sum(pr[i]);
        if (lane == 0) s_sh[wrp + 8 * i] = s + bias;
    }
    if (wrp == 0 && start > 0) {
        float s = warp_sum(pprev);
        if (lane == 0) sprev_sh = s + bias;
    }
    __syncthreads();

    if (tid < CHUNK) {
        float logit;
        if (tid == 0) logit = (start == 0) ? 0.0f : sprev_sh;
        else          logit = s_sh[tid - 1];
        e_sh[tid] = expf(logit);
    }
    __syncthreads();

    {
        float4 acc = make_float4(0.f, 0.f, 0.f, 0.f);
        #pragma unroll
        for (int i = 0; i < 8; i++) {
            const float e = e_sh[wrp + 8 * i];
            acc.x += e * v[i].x; acc.y += e * v[i].y;
            acc.z += e * v[i].z; acc.w += e * v[i].w;
        }
        *(float4*)&partial[wrp][lane * 4] = acc;
    }
    __syncthreads();
    if (tid < HDIM) {
        float s = 0.0f;
        #pragma unroll
        for (int w = 0; w < 8; w++) s += partial[w][tid];
        g_pvec[((size_t)b * NCHUNK + chunk) * HDIM + tid] = s;
    }
    if (wrp == 0) {
        float es = e_sh[lane] + e_sh[lane + 32];
        es = warp_sum(es);
        if (lane == 0) g_psum[b * NCHUNK + chunk] = es;
    }
}

// ---------------------------------------------------------------------------
// Kernel 2: decode, thread-per-output split-K GEMVs (no shfl chains, no
// weight staging). 1024 threads per block, one block per batch element.
// ---------------------------------------------------------------------------
__global__ void __launch_bounds__(1024) decode_kernel(
    const float* __restrict__ input,
    const float* __restrict__ c0,
    const float* __restrict__ inp_W, const float* __restrict__ inp_b,
    const float* __restrict__ W_ih0,
    const float* __restrict__ W_ih1,
    float* __restrict__ out)
{
    __shared__ __align__(16) float cat_sh[256];
    __shared__ __align__(16) float xin_sh[HDIM];
    __shared__ __align__(16) float h1_sh[HDIM];
    __shared__ float c0_sh[2 * HDIM];
    __shared__ float vred[8][HDIM];
    __shared__ float sarr[NCHUNK];
    __shared__ float xpart[8][HDIM];    // xin split-K partials
    __shared__ float gpart[2][512];     // gate split-K partials
    __shared__ float pre_sh[512];
    __shared__ float pre1_sh[512];
    __shared__ float S_sh;

    const int b = blockIdx.x;
    const int tid = threadIdx.x, lane = tid & 31, wrp = tid >> 5;

    // Early: c0, pre0, pre1 into smem (independent loads, overlap stage0)
    if (tid < HDIM) {
        c0_sh[tid]        = c0[b * HDIM + tid];
        c0_sh[HDIM + tid] = c0[BATCH * HDIM + b * HDIM + tid];
    }
    if (tid < 512) pre_sh[tid]  = g_pre0[b * 512 + tid];
    else           pre1_sh[tid - 512] = g_pre1[b * 512 + (tid - 512)];

    // Stage 0: reduce attention partials
    if (tid < NCHUNK) sarr[tid] = g_psum[b * NCHUNK + tid];
    {
        const int h = tid & 127, grp = (tid >> 7) & 7;
        float v = 0.0f;
        #pragma unroll
        for (int c = 0; c < 8; c++)
            v += g_pvec[((size_t)b * NCHUNK + grp * 8 + c) * HDIM + h];
        vred[grp][h] = v;
    }
    __syncthreads();
    float vcol = 0.0f;
    if (tid < HDIM) {
        #pragma unroll
        for (int g = 0; g < 8; g++) vcol += vred[g][tid];
    }
    if (wrp == 0) {
        float s = sarr[lane] + sarr[lane + 32];
        s = warp_sum(s);
        if (lane == 0) S_sh = s;
    }
    __syncthreads();
    if (tid < HDIM) {
        cat_sh[tid]        = vcol / S_sh;
        cat_sh[HDIM + tid] = input[b * HDIM + tid];
    }
    __syncthreads();

    // xin = cat @ inp_W.T + inp_b
    // thread-per-output split-K: o = tid>>3 (0..127), part = tid&7 (32 elems)
    {
        const int o = tid >> 3, part = tid & 7;
        const float4* wrow = (const float4*)(inp_W + o * 256) + part * 8;
        const float4* cv   = (const float4*)cat_sh + part * 8;
        float acc = 0.0f;
        #pragma unroll
        for (int j = 0; j < 8; j++) acc += dot4(wrow[j], cv[j]);
        xpart[part][o] = acc;
    }
    __syncthreads();
    if (tid < HDIM) {
        float s = 0.0f;
        #pragma unroll
        for (int p = 0; p < 8; p++) s += xpart[p][tid];
        xin_sh[tid] = s + inp_b[tid];
    }
    __syncthreads();

    float* out_h1 = out + 8192 + b * HDIM;
    float* out_h2 = out + 16384 + b * HDIM;
    float* out_c1 = out + 24576 + b * HDIM;
    float* out_c2 = out + 32768 + b * HDIM;
    float* out_y  = out + b * HDIM;

    // LSTM layer 0: k = tid&511, half = tid>>9 covers 64 elems (16 float4)
    {
        const int k = tid & 511, half = tid >> 9;
        const float4* wrow = (const float4*)(W_ih0 + k * HDIM) + half * 16;
        const float4* xv   = (const float4*)xin_sh + half * 16;
        float acc = 0.0f;
        #pragma unroll
        for (int j = 0; j < 16; j++) acc += dot4(wrow[j], xv[j]);
        gpart[half][k] = acc;
    }
    __syncthreads();
    if (tid < HDIM) {
        const float ig = gpart[0][tid]       + gpart[1][tid]       + pre_sh[tid];
        const float fg = gpart[0][128 + tid] + gpart[1][128 + tid] + pre_sh[128 + tid];
        const float gg = gpart[0][256 + tid] + gpart[1][256 + tid] + pre_sh[256 + tid];
        const float og = gpart[0][384 + tid] + gpart[1][384 + tid] + pre_sh[384 + tid];
        const float cn = sigmoidf_(fg) * c0_sh[tid] + sigmoidf_(ig) * tanhf(gg);
        const float hn = sigmoidf_(og) * tanhf(cn);
        h1_sh[tid]  = hn;
        out_c1[tid] = cn;
        out_h1[tid] = hn;
    }
    __syncthreads();

    // LSTM layer 1
    {
        const int k = tid & 511, half = tid >> 9;
        const float4* wrow = (const float4*)(W_ih1 + k * HDIM) + half * 16;
        const float4* hv   = (const float4*)h1_sh + half * 16;
        float acc = 0.0f;
        #pragma unroll
        for (int j = 0; j < 16; j++) acc += dot4(wrow[j], hv[j]);
        gpart[half][k] = acc;
    }
    __syncthreads();
    if (tid < HDIM) {
        const float ig = gpart[0][tid]       + gpart[1][tid]       + pre1_sh[tid];
        const float fg = gpart[0][128 + tid] + gpart[1][128 + tid] + pre1_sh[128 + tid];
        const float gg = gpart[0][256 + tid] + gpart[1][256 + tid] + pre1_sh[256 + tid];
        const float og = gpart[0][384 + tid] + gpart[1][384 + tid] + pre1_sh[384 + tid];
        const float cn = sigmoidf_(fg) * c0_sh[HDIM + tid] + sigmoidf_(ig) * tanhf(gg);
        const float hn = sigmoidf_(og) * tanhf(cn);
        out_c2[tid] = cn;
        out_h2[tid] = hn;
        out_y[tid]  = hn;
    }
}

extern "C" void kernel_launch(void* const* d_in, const int* in_sizes, int n_in,
                              void* d_out, int out_size)
{
    const float* input  = (const float*)d_in[0];
    const float* h0     = (const float*)d_in[1];
    const float* c0     = (const float*)d_in[2];
    const float* enc    = (const float*)d_in[3];
    const float* attW   = (const float*)d_in[4];
    const float* attb   = (const float*)d_in[5];
    const float* inp_W  = (const float*)d_in[6];
    const float* inp_b  = (const float*)d_in[7];
    const float* W_ih0  = (const float*)d_in[8];
    const float* W_hh0  = (const float*)d_in[9];
    const float* b_ih0  = (const float*)d_in[10];
    const float* b_hh0  = (const float*)d_in[11];
    const float* W_ih1  = (const float*)d_in[12];
    const float* W_hh1  = (const float*)d_in[13];
    const float* b_ih1  = (const float*)d_in[14];
    const float* b_hh1  = (const float*)d_in[15];
    float* out = (float*)d_out;

    attn_pre_kernel<<<NPRE + NCHUNK * BATCH, 256>>>(
        enc, h0, c0, attW, attb,
        W_hh0, b_ih0, b_hh0, W_hh1, b_ih1, b_hh1);
    decode_kernel<<<BATCH, 1024>>>(input, c0, inp_W, inp_b, W_ih0, W_ih1, out);
}

// round 9
// speedup vs baseline: 1.3422x; 1.3422x over previous
#include <cuda_runtime.h>
#include <cstdint>
#include <math.h>

#define WTOT 4096
#define CHUNK 64
#define HDIM 128
#define BATCH 64
#define NCHUNK (WTOT / CHUNK)
#define NPRE 512

__device__ __align__(16) float g_pvec[BATCH * NCHUNK * HDIM];
__device__ __align__(16) float g_psum[BATCH * NCHUNK];
__device__ __align__(16) float g_pre0[BATCH * 512];
__device__ __align__(16) float g_pre1[BATCH * 512];

__device__ __forceinline__ float warp_sum(float p) {
    #pragma unroll
    for (int o = 16; o > 0; o >>= 1) p += __shfl_down_sync(0xffffffffu, p, o);
    return p;
}

__device__ __forceinline__ float sigmoidf_(float x) {
    return 1.0f / (1.0f + expf(-x));
}

__device__ __forceinline__ float dot4(float4 a, float4 b) {
    return a.x * b.x + a.y * b.y + a.z * b.z + a.w * b.w;
}

// ---------------------------------------------------------------------------
// Kernel 1: blocks [0,NPRE): hh-gate precompute; rest: register-resident
// attention pass (unchanged from R8 — proven).
// ---------------------------------------------------------------------------
__global__ void __launch_bounds__(256) attn_pre_kernel(
    const float* __restrict__ enc,
    const float* __restrict__ h0,
    const float* __restrict__ c0,
    const float* __restrict__ attW,
    const float* __restrict__ attb,
    const float* __restrict__ W_hh0,
    const float* __restrict__ b_ih0, const float* __restrict__ b_hh0,
    const float* __restrict__ W_hh1,
    const float* __restrict__ b_ih1, const float* __restrict__ b_hh1)
{
    const int tid  = threadIdx.x;
    const int lane = tid & 31;
    const int wrp  = tid >> 5;

    if (blockIdx.x < NPRE) {
        const int b  = blockIdx.x >> 3;
        const int k0 = (blockIdx.x & 7) * 64;
        const float4 hv0 = ((const float4*)(h0 + b * HDIM))[lane];
        const float4 hv1 = ((const float4*)(h0 + BATCH * HDIM + b * HDIM))[lane];
        #pragma unroll 4
        for (int t = 0; t < 8; t++) {
            const int k = k0 + wrp * 8 + t;
            float p0 = dot4(((const float4*)(W_hh0 + k * HDIM))[lane], hv0);
            p0 = warp_sum(p0);
            if (lane == 0) g_pre0[b * 512 + k] = p0 + b_ih0[k] + b_hh0[k];
        }
        #pragma unroll 4
        for (int t = 0; t < 8; t++) {
            const int k = k0 + wrp * 8 + t;
            float p1 = dot4(((const float4*)(W_hh1 + k * HDIM))[lane], hv1);
            p1 = warp_sum(p1);
            if (lane == 0) g_pre1[b * 512 + k] = p1 + b_ih1[k] + b_hh1[k];
        }
        return;
    }

    __shared__ float s_sh[CHUNK];
    __shared__ float e_sh[CHUNK];
    __shared__ float red[4];
    __shared__ float bias_sh;
    __shared__ float sprev_sh;
    __shared__ __align__(16) float partial[8][136];

    const int cid   = blockIdx.x - NPRE;
    const int chunk = cid & (NCHUNK - 1);
    const int b     = cid >> 6;
    const int start = chunk * CHUNK;

    const float4* src = (const float4*)(enc + ((size_t)b * WTOT + start) * HDIM);
    float4 v[8];
    #pragma unroll
    for (int i = 0; i < 8; i++) v[i] = src[tid + 256 * i];
    float4 vprev = make_float4(0.f, 0.f, 0.f, 0.f);
    if (wrp == 0 && start > 0)
        vprev = ((const float4*)(enc + ((size_t)b * WTOT + start - 1) * HDIM))[lane];

    const float4 wv = ((const float4*)attW)[lane];

    if (tid < HDIM) {
        float p = h0[BATCH * HDIM + b * HDIM + tid]
                * c0[BATCH * HDIM + b * HDIM + tid]
                * attW[HDIM + tid];
        p = warp_sum(p);
        if (lane == 0) red[wrp] = p;
    }
    __syncthreads();
    if (tid == 0) bias_sh = red[0] + red[1] + red[2] + red[3] + attb[0];

    float pr[8];
    #pragma unroll
    for (int i = 0; i < 8; i++) pr[i] = dot4(v[i], wv);
    float pprev = dot4(vprev, wv);
    __syncthreads();
    const float bias = bias_sh;
    #pragma unroll
    for (int i = 0; i < 8; i++) {
        float s = warp_sum(pr[i]);
        if (lane == 0) s_sh[wrp + 8 * i] = s + bias;
    }
    if (wrp == 0 && start > 0) {
        float s = warp_sum(pprev);
        if (lane == 0) sprev_sh = s + bias;
    }
    __syncthreads();

    if (tid < CHUNK) {
        float logit;
        if (tid == 0) logit = (start == 0) ? 0.0f : sprev_sh;
        else          logit = s_sh[tid - 1];
        e_sh[tid] = expf(logit);
    }
    __syncthreads();

    {
        float4 acc = make_float4(0.f, 0.f, 0.f, 0.f);
        #pragma unroll
        for (int i = 0; i < 8; i++) {
            const float e = e_sh[wrp + 8 * i];
            acc.x += e * v[i].x; acc.y += e * v[i].y;
            acc.z += e * v[i].z; acc.w += e * v[i].w;
        }
        *(float4*)&partial[wrp][lane * 4] = acc;
    }
    __syncthreads();
    if (tid < HDIM) {
        float s = 0.0f;
        #pragma unroll
        for (int w = 0; w < 8; w++) s += partial[w][tid];
        g_pvec[((size_t)b * NCHUNK + chunk) * HDIM + tid] = s;
    }
    if (wrp == 0) {
        float es = e_sh[lane] + e_sh[lane + 32];
        es = warp_sum(es);
        if (lane == 0) g_psum[b * NCHUNK + chunk] = es;
    }
}

// ---------------------------------------------------------------------------
// Pipelined, coalesced warp-dot over 16 gates per warp: weights for the next
// 4-gate group load while the current group's 4 interleaved shfl chains run.
// ---------------------------------------------------------------------------
__device__ __forceinline__ void lstm_gates(
    const float* __restrict__ W, const float4 xv,
    const float* __restrict__ pre_sh, float* gate_sh,
    int wrp, int lane)
{
    const int kbase = wrp * 16;
    float4 w[2][4];
    #pragma unroll
    for (int t = 0; t < 4; t++)
        w[0][t] = ((const float4*)(W + (kbase + t) * HDIM))[lane];
    #pragma unroll
    for (int g = 0; g < 4; g++) {
        if (g < 3) {
            #pragma unroll
            for (int t = 0; t < 4; t++)
                w[(g + 1) & 1][t] =
                    ((const float4*)(W + (kbase + (g + 1) * 4 + t) * HDIM))[lane];
        }
        float acc[4];
        #pragma unroll
        for (int t = 0; t < 4; t++) acc[t] = dot4(w[g & 1][t], xv);
        #pragma unroll
        for (int o = 16; o > 0; o >>= 1) {
            #pragma unroll
            for (int t = 0; t < 4; t++)
                acc[t] += __shfl_down_sync(0xffffffffu, acc[t], o);
        }
        if (lane == 0) {
            #pragma unroll
            for (int t = 0; t < 4; t++) {
                const int k = kbase + g * 4 + t;
                gate_sh[k] = acc[t] + pre_sh[k];
            }
        }
    }
}

// ---------------------------------------------------------------------------
// Kernel 2: decode, one block per batch, 1024 threads.
// ---------------------------------------------------------------------------
__global__ void __launch_bounds__(1024) decode_kernel(
    const float* __restrict__ input,
    const float* __restrict__ c0,
    const float* __restrict__ inp_W, const float* __restrict__ inp_b,
    const float* __restrict__ W_ih0,
    const float* __restrict__ W_ih1,
    float* __restrict__ out)
{
    __shared__ __align__(16) float cat_sh[256];
    __shared__ __align__(16) float xin_sh[HDIM];
    __shared__ __align__(16) float h1_sh[HDIM];
    __shared__ float gate_sh[512];
    __shared__ float c0_sh[2 * HDIM];
    __shared__ float vred[8][HDIM];
    __shared__ float sarr[NCHUNK];
    __shared__ float pre0_sh[512];
    __shared__ float pre1_sh[512];
    __shared__ float S_sh;

    const int b = blockIdx.x;
    const int tid = threadIdx.x, lane = tid & 31, wrp = tid >> 5;

    // Early independent loads (overlap everything below)
    if (tid < HDIM) {
        c0_sh[tid]        = c0[b * HDIM + tid];
        c0_sh[HDIM + tid] = c0[BATCH * HDIM + b * HDIM + tid];
    }
    if (tid < 512) pre0_sh[tid] = g_pre0[b * 512 + tid];
    else           pre1_sh[tid - 512] = g_pre1[b * 512 + (tid - 512)];

    // Stage 0: reduce attention partials
    if (tid < NCHUNK) sarr[tid] = g_psum[b * NCHUNK + tid];
    {
        const int h = tid & 127, grp = (tid >> 7) & 7;
        float v = 0.0f;
        #pragma unroll
        for (int c = 0; c < 8; c++)
            v += g_pvec[((size_t)b * NCHUNK + grp * 8 + c) * HDIM + h];
        vred[grp][h] = v;
    }
    __syncthreads();
    float vcol = 0.0f;
    if (tid < HDIM) {
        #pragma unroll
        for (int g = 0; g < 8; g++) vcol += vred[g][tid];
    }
    if (wrp == 0) {
        float s = sarr[lane] + sarr[lane + 32];
        s = warp_sum(s);
        if (lane == 0) S_sh = s;
    }
    __syncthreads();
    if (tid < HDIM) {
        cat_sh[tid]        = vcol / S_sh;
        cat_sh[HDIM + tid] = input[b * HDIM + tid];
    }
    __syncthreads();

    // xin: 32 warps x 4 outputs, K=256. Prefetch all 8 weight float4 first,
    // then 4 interleaved shfl chains.
    {
        const float4 c0v = ((const float4*)cat_sh)[lane];
        const float4 c1v = ((const float4*)cat_sh)[lane + 32];
        float4 a0[4], a1[4];
        #pragma unroll
        for (int t = 0; t < 4; t++) {
            const float4* wrow = (const float4*)(inp_W + (wrp * 4 + t) * 256);
            a0[t] = wrow[lane];
            a1[t] = wrow[lane + 32];
        }
        float acc[4];
        #pragma unroll
        for (int t = 0; t < 4; t++)
            acc[t] = dot4(a0[t], c0v) + dot4(a1[t], c1v);
        #pragma unroll
        for (int o = 16; o > 0; o >>= 1) {
            #pragma unroll
            for (int t = 0; t < 4; t++)
                acc[t] += __shfl_down_sync(0xffffffffu, acc[t], o);
        }
        if (lane == 0) {
            #pragma unroll
            for (int t = 0; t < 4; t++) {
                const int i = wrp * 4 + t;
                xin_sh[i] = acc[t] + inp_b[i];
            }
        }
    }
    __syncthreads();

    float* out_h1 = out + 8192 + b * HDIM;
    float* out_h2 = out + 16384 + b * HDIM;
    float* out_c1 = out + 24576 + b * HDIM;
    float* out_c2 = out + 32768 + b * HDIM;
    float* out_y  = out + b * HDIM;

    // LSTM layer 0
    lstm_gates(W_ih0, ((const float4*)xin_sh)[lane], pre0_sh, gate_sh, wrp, lane);
    __syncthreads();
    if (tid < HDIM) {
        const float ig = gate_sh[tid];
        const float fg = gate_sh[128 + tid];
        const float gg = gate_sh[256 + tid];
        const float og = gate_sh[384 + tid];
        const float cn = sigmoidf_(fg) * c0_sh[tid] + sigmoidf_(ig) * tanhf(gg);
        const float hn = sigmoidf_(og) * tanhf(cn);
        h1_sh[tid]  = hn;
        out_c1[tid] = cn;
        out_h1[tid] = hn;
    }
    __syncthreads();

    // LSTM layer 1
    lstm_gates(W_ih1, ((const float4*)h1_sh)[lane], pre1_sh, gate_sh, wrp, lane);
    __syncthreads();
    if (tid < HDIM) {
        const float ig = gate_sh[tid];
        const float fg = gate_sh[128 + tid];
        const float gg = gate_sh[256 + tid];
        const float og = gate_sh[384 + tid];
        const float cn = sigmoidf_(fg) * c0_sh[HDIM + tid] + sigmoidf_(ig) * tanhf(gg);
        const float hn = sigmoidf_(og) * tanhf(cn);
        out_c2[tid] = cn;
        out_h2[tid] = hn;
        out_y[tid]  = hn;
    }
}

extern "C" void kernel_launch(void* const* d_in, const int* in_sizes, int n_in,
                              void* d_out, int out_size)
{
    const float* input  = (const float*)d_in[0];
    const float* h0     = (const float*)d_in[1];
    const float* c0     = (const float*)d_in[2];
    const float* enc    = (const float*)d_in[3];
    const float* attW   = (const float*)d_in[4];
    const float* attb   = (const float*)d_in[5];
    const float* inp_W  = (const float*)d_in[6];
    const float* inp_b  = (const float*)d_in[7];
    const float* W_ih0  = (const float*)d_in[8];
    const float* W_hh0  = (const float*)d_in[9];
    const float* b_ih0  = (const float*)d_in[10];
    const float* b_hh0  = (const float*)d_in[11];
    const float* W_ih1  = (const float*)d_in[12];
    const float* W_hh1  = (const float*)d_in[13];
    const float* b_ih1  = (const float*)d_in[14];
    const float* b_hh1  = (const float*)d_in[15];
    float* out = (float*)d_out;

    attn_pre_kernel<<<NPRE + NCHUNK * BATCH, 256>>>(
        enc, h0, c0, attW, attb,
        W_hh0, b_ih0, b_hh0, W_hh1, b_ih1, b_hh1);
    decode_kernel<<<BATCH, 1024>>>(input, c0, inp_W, inp_b, W_ih0, W_ih1, out);
}